// round 11
// baseline (speedup 1.0000x reference)
#include <cuda_runtime.h>
#include <math.h>
#include <stdint.h>

#define B   8
#define N1  32768
#define NP1 512
#define NS1 32
#define N2  512
#define NP2 256
#define NS2 64
#define CAP 128
#define CCAP 96

#define FCL 8          // cluster size for fps1
#define FPTS 4096      // points per CTA
#define FPPT 8         // points per thread (512 threads)

#define G1  16         // centroids per bq1 block
#define SP1 8          // point splits per centroid group

typedef unsigned long long ull;

// ---------------- scratch (device globals; no allocations) ----------------
__device__ float g_w1t [6  * 64 ];
__device__ float g_w2t [64 * 64 ];
__device__ float g_w3t [64 * 128];
__device__ float g_w1t2[131 * 128];
__device__ float g_w2t2[128 * 128];
__device__ float g_w3t2[128 * 285];

__device__ float g_norms1[B * N1];
__device__ int   g_fps1 [B * NP1];
__device__ float g_nx1  [B * NP1 * 3];
__device__ int   g_cnt1 [B * NP1];
__device__ int   g_list1[B * NP1 * 64];
__device__ float g_feat1[B * NP1 * 128];
__device__ int   g_ccnt1[B * NP1];
__device__ int   g_coll1[B * NP1 * CCAP];

__device__ float g_norms2[B * N2];
__device__ int   g_fps2 [B * NP2];
__device__ float g_nx2  [B * NP2 * 3];
__device__ int   g_cnt2 [B * NP2];
__device__ int   g_list2[B * NP2 * 64];

// ---------------- cluster helpers ------------------------------------------
__device__ __forceinline__ uint32_t s2u(const void* p) {
    return (uint32_t)__cvta_generic_to_shared(p);
}
__device__ __forceinline__ unsigned cl_rank() {
    unsigned r; asm("mov.u32 %0, %%cluster_ctarank;" : "=r"(r)); return r;
}
__device__ __forceinline__ void cluster_sync() {
    asm volatile("barrier.cluster.arrive.aligned;" ::: "memory");
    asm volatile("barrier.cluster.wait.aligned;" ::: "memory");
}
__device__ __forceinline__ void st_remote_u64(uint32_t laddr, unsigned rank, ull v) {
    asm volatile("{ .reg .b32 ra; mapa.shared::cluster.u32 ra, %0, %1; "
                 "st.shared::cluster.b64 [ra], %2; }"
                 :: "r"(laddr), "r"(rank), "l"(v) : "memory");
}
__device__ __forceinline__ void arrive_remote(uint32_t lbar, unsigned rank) {
    asm volatile("{ .reg .b32 ra; mapa.shared::cluster.u32 ra, %0, %1; "
                 "mbarrier.arrive.release.cluster.shared::cluster.b64 _, [ra]; }"
                 :: "r"(lbar), "r"(rank) : "memory");
}
// acquire.cta wait (sanctioned pattern; remote data already landed in OUR smem)
__device__ __forceinline__ void mbar_wait_cta(uint32_t mbar, unsigned parity) {
    asm volatile(
        "{\n\t"
        ".reg .pred P1;\n\t"
        "WAIT_LOOP_%=:\n\t"
        "mbarrier.try_wait.parity.acquire.cta.shared::cta.b64 P1, [%0], %1, 0x989680;\n\t"
        "@P1 bra.uni WAIT_DONE_%=;\n\t"
        "bra.uni WAIT_LOOP_%=;\n\t"
        "WAIT_DONE_%=:\n\t"
        "}" :: "r"(mbar), "r"(parity) : "memory");
}

// ---------------- weight transpose + counter init ---------------------------
__global__ void k_transpose_all(const float* __restrict__ w1, const float* __restrict__ w2,
                                const float* __restrict__ w3, const float* __restrict__ u1,
                                const float* __restrict__ u2, const float* __restrict__ u3) {
    int i = blockIdx.x * 256 + threadIdx.x;
    if (i < 384) {                              // 64x6
        int o = i / 6, c = i % 6;               g_w1t [c * 64  + o] = w1[i];
    } else if (i < 4480) {                      // 64x64
        int j = i - 384;  int o = j / 64,  c = j % 64;  g_w2t [c * 64  + o] = w2[j];
    } else if (i < 12672) {                     // 128x64
        int j = i - 4480; int o = j / 64,  c = j % 64;  g_w3t [c * 128 + o] = w3[j];
    } else if (i < 29440) {                     // 128x131
        int j = i - 12672;int o = j / 131, c = j % 131; g_w1t2[c * 128 + o] = u1[j];
    } else if (i < 45824) {                     // 128x128
        int j = i - 29440;int o = j / 128, c = j % 128; g_w2t2[c * 128 + o] = u2[j];
    } else if (i < 82304) {                     // 285x128
        int j = i - 45824;int o = j / 128, c = j % 128; g_w3t2[c * 285 + o] = u3[j];
    } else if (i < 82304 + B * NP1) {           // zero bq1 collection counters
        g_ccnt1[i - 82304] = 0;
    }
}

// ---------------- squared norms --------------------------------------------
__global__ void k_norms1(const float* __restrict__ xyz) {
    int i = blockIdx.x * 256 + threadIdx.x;
    if (i < B * N1) {
        int b = i >> 15, n = i & (N1 - 1);
        const float* base = xyz + (size_t)b * 6 * N1;
        float x = base[n], y = base[N1 + n], z = base[2 * N1 + n];
        g_norms1[i] = (x * x + y * y) + z * z;
    }
}

__global__ void k_norms2() {
    int i = blockIdx.x * 256 + threadIdx.x;
    if (i < B * N2) {
        float x = g_nx1[i * 3], y = g_nx1[i * 3 + 1], z = g_nx1[i * 3 + 2];
        g_norms2[i] = (x * x + y * y) + z * z;
    }
}

// ---------------- FPS stage 1: cluster of 8 CTAs per batch ------------------
// Agent = warp 15 (hi-wid-first arbiter priority). Exchange carries only
// (value, coords); tie-break across CTAs = rank order == index order.
__global__ void __launch_bounds__(512, 1) __cluster_dims__(FCL, 1, 1)
k_fps1(const float* __restrict__ xyz) {
    int b = blockIdx.x / FCL;
    unsigned rank = cl_rank();
    int tid = threadIdx.x;
    int lane = tid & 31, warp = tid >> 5;
    const float* X = xyz + (size_t)b * 6 * N1;
    const float* Y = X + N1;
    const float* Z = X + 2 * N1;
    unsigned base = rank * FPTS;

    float px[FPPT], py[FPPT], pz[FPPT], dist[FPPT];
#pragma unroll
    for (int j = 0; j < FPPT; ++j) {
        int p = base + j * 512 + tid;
        px[j] = X[p]; py[j] = Y[p]; pz[j] = Z[p];
        dist[j] = 1e10f;
    }

    __shared__ unsigned s_wv[16], s_wbi[16];
    __shared__ float s_wcx[16], s_wcy[16], s_wcz[16];
    __shared__ ull   s_A[2][FCL];   // {cx_bits<<32 | val_bits}
    __shared__ ull   s_B[2][FCL];   // {cz_bits<<32 | cy_bits}
    __shared__ unsigned s_mybi;
    __shared__ ull   s_mbar;

    uint32_t bar = s2u(&s_mbar);
    if (tid == 0) {
        asm volatile("mbarrier.init.shared.b64 [%0], %1;" :: "r"(bar), "r"((unsigned)FCL) : "memory");
        asm volatile("fence.mbarrier_init.release.cluster;" ::: "memory");
    }
    __syncthreads();
    cluster_sync();

    float cx = X[0], cy = Y[0], cz = Z[0];
    if (rank == 0 && tid == 0) {
        g_fps1[b * NP1] = 0;
        g_nx1[(b * NP1) * 3 + 0] = cx;
        g_nx1[(b * NP1) * 3 + 1] = cy;
        g_nx1[(b * NP1) * 3 + 2] = cz;
    }

    for (int it = 0; it < NP1 - 1; ++it) {
        unsigned par = (unsigned)(it & 1);
        // update dists (parallel) + thread-local argmax via packed-key tree
        ull kk[FPPT];
#pragma unroll
        for (int j = 0; j < FPPT; ++j) {
            float dx = px[j] - cx, dy = py[j] - cy, dz = pz[j] - cz;
            float d  = dx * dx + dy * dy + dz * dz;
            float nd = fminf(dist[j], d);
            dist[j] = nd;
            unsigned bij = base + (unsigned)(j * 512 + tid);
            kk[j] = ((ull)__float_as_uint(nd) << 32) | (ull)(0xFFFFFFFFu - bij);
        }
#pragma unroll
        for (int s = FPPT / 2; s; s >>= 1)
#pragma unroll
            for (int i = 0; i < s; ++i)
                if (kk[i + s] > kk[i]) kk[i] = kk[i + s];
        unsigned vb = (unsigned)(kk[0] >> 32);
        unsigned bi = 0xFFFFFFFFu - (unsigned)(kk[0] & 0xFFFFFFFFull);

        // warp reduce via REDUX (max value, then min index among max holders)
        unsigned wmax = __reduce_max_sync(0xFFFFFFFFu, vb);
        unsigned cand = (vb == wmax) ? bi : 0xFFFFFFFFu;
        unsigned wbi  = __reduce_min_sync(0xFFFFFFFFu, cand);

        // winner coords from winner thread's registers
        {
            unsigned lw = wbi & 31u;
            unsigned jw = (wbi & 4095u) >> 9;
            float sx = px[0], sy = py[0], sz = pz[0];
#pragma unroll
            for (int j = 1; j < FPPT; ++j) {
                if (jw == (unsigned)j) { sx = px[j]; sy = py[j]; sz = pz[j]; }
            }
            sx = __shfl_sync(0xFFFFFFFFu, sx, lw);
            sy = __shfl_sync(0xFFFFFFFFu, sy, lw);
            sz = __shfl_sync(0xFFFFFFFFu, sz, lw);
            if (lane == 0) {
                s_wv[warp] = wmax; s_wbi[warp] = wbi;
                s_wcx[warp] = sx;  s_wcy[warp] = sy; s_wcz[warp] = sz;
            }
        }
        __syncthreads();

        if (warp == 15) {   // highest-priority warp is the critical agent
            unsigned v  = (lane < 16) ? s_wv[lane]  : 0u;
            unsigned bw = (lane < 16) ? s_wbi[lane] : 0xFFFFFFFFu;
            unsigned vmax = __reduce_max_sync(0xFFFFFFFFu, v);
            unsigned c2   = (v == vmax && lane < 16) ? bw : 0xFFFFFFFFu;
            unsigned bbi  = __reduce_min_sync(0xFFFFFFFFu, c2);
            if (lane < FCL) {
                unsigned w = (bbi & 511u) >> 5;        // winning warp in this CTA
                float bx = s_wcx[w], by = s_wcy[w], bz = s_wcz[w];
                if ((unsigned)lane == rank) s_mybi = bbi;   // before release-arrive to self
                ull A = ((ull)__float_as_uint(bx) << 32) | (ull)vmax;
                ull Bv = ((ull)__float_as_uint(bz) << 32) | (ull)__float_as_uint(by);
                st_remote_u64(s2u(&s_A[par][rank]), (unsigned)lane, A);
                st_remote_u64(s2u(&s_B[par][rank]), (unsigned)lane, Bv);
                arrive_remote(bar, (unsigned)lane);
            }
        }

        mbar_wait_cta(bar, par);

        // rank-ordered strict-> scan over values == first-index tie-break
        ull a0 = s_A[par][0], a1 = s_A[par][1], a2 = s_A[par][2], a3 = s_A[par][3];
        ull a4 = s_A[par][4], a5 = s_A[par][5], a6 = s_A[par][6], a7 = s_A[par][7];
        unsigned bv = (unsigned)a0; int bs = 0; ull bA = a0;
        if ((unsigned)a1 > bv) { bv = (unsigned)a1; bs = 1; bA = a1; }
        if ((unsigned)a2 > bv) { bv = (unsigned)a2; bs = 2; bA = a2; }
        if ((unsigned)a3 > bv) { bv = (unsigned)a3; bs = 3; bA = a3; }
        if ((unsigned)a4 > bv) { bv = (unsigned)a4; bs = 4; bA = a4; }
        if ((unsigned)a5 > bv) { bv = (unsigned)a5; bs = 5; bA = a5; }
        if ((unsigned)a6 > bv) { bv = (unsigned)a6; bs = 6; bA = a6; }
        if ((unsigned)a7 > bv) { bv = (unsigned)a7; bs = 7; bA = a7; }
        ull bB = s_B[par][bs];
        cx = __uint_as_float((unsigned)(bA >> 32));
        cy = __uint_as_float((unsigned)bB);
        cz = __uint_as_float((unsigned)(bB >> 32));

        if ((unsigned)bs == rank && tid == 0) {   // winner writes outputs (off path)
            g_fps1[b * NP1 + it + 1] = (int)s_mybi;
            g_nx1[(b * NP1 + it + 1) * 3 + 0] = cx;
            g_nx1[(b * NP1 + it + 1) * 3 + 1] = cy;
            g_nx1[(b * NP1 + it + 1) * 3 + 2] = cz;
        }
    }
    cluster_sync();
}

// ---------------- FPS stage 2: one warp per batch, all-register -------------
__global__ void __launch_bounds__(32, 1) k_fps2() {
    int b = blockIdx.x;
    int lane = threadIdx.x;

    float px[16], py[16], pz[16], dist[16];
#pragma unroll
    for (int j = 0; j < 16; ++j) {
        int p = j * 32 + lane;
        px[j] = g_nx1[(b * NP1 + p) * 3 + 0];
        py[j] = g_nx1[(b * NP1 + p) * 3 + 1];
        pz[j] = g_nx1[(b * NP1 + p) * 3 + 2];
        dist[j] = 1e10f;
    }

    unsigned far = 0;
    float cx = __shfl_sync(0xFFFFFFFFu, px[0], 0);
    float cy = __shfl_sync(0xFFFFFFFFu, py[0], 0);
    float cz = __shfl_sync(0xFFFFFFFFu, pz[0], 0);

    for (int it = 0; it < NP2; ++it) {
        if (lane == 0) {
            g_fps2[b * NP2 + it] = (int)far;
            g_nx2[(b * NP2 + it) * 3 + 0] = cx;
            g_nx2[(b * NP2 + it) * 3 + 1] = cy;
            g_nx2[(b * NP2 + it) * 3 + 2] = cz;
        }
        ull kk[16];
#pragma unroll
        for (int j = 0; j < 16; ++j) {
            float dx = px[j] - cx, dy = py[j] - cy, dz = pz[j] - cz;
            float d  = dx * dx + dy * dy + dz * dz;
            float nd = fminf(dist[j], d);
            dist[j] = nd;
            unsigned bij = (unsigned)(j * 32 + lane);
            kk[j] = ((ull)__float_as_uint(nd) << 32) | (ull)(0xFFFFFFFFu - bij);
        }
#pragma unroll
        for (int s = 8; s; s >>= 1)
#pragma unroll
            for (int i = 0; i < s; ++i)
                if (kk[i + s] > kk[i]) kk[i] = kk[i + s];
        unsigned vb = (unsigned)(kk[0] >> 32);
        unsigned bi = 0xFFFFFFFFu - (unsigned)(kk[0] & 0xFFFFFFFFull);

        unsigned wmax = __reduce_max_sync(0xFFFFFFFFu, vb);
        unsigned cand = (vb == wmax) ? bi : 0xFFFFFFFFu;
        unsigned wbi  = __reduce_min_sync(0xFFFFFFFFu, cand);

        unsigned lw = wbi & 31u;
        unsigned jw = wbi >> 5;
        float sx = px[0], sy = py[0], sz = pz[0];
#pragma unroll
        for (int j = 1; j < 16; ++j) {
            if (jw == (unsigned)j) { sx = px[j]; sy = py[j]; sz = pz[j]; }
        }
        cx = __shfl_sync(0xFFFFFFFFu, sx, lw);
        cy = __shfl_sync(0xFFFFFFFFu, sy, lw);
        cz = __shfl_sync(0xFFFFFFFFu, sz, lw);
        far = wbi;
    }
}

// ---------------- ball query 1: 16 centroids x 8 point-splits ---------------
__global__ void __launch_bounds__(256) k_bq1c(const float* __restrict__ xyz) {
    int bid   = blockIdx.x;
    int b     = bid / (32 * SP1);
    int rem   = bid % (32 * SP1);
    int grp   = rem / SP1;
    int split = rem % SP1;
    int g0    = grp * G1;
    int t     = threadIdx.x;

    __shared__ float s_cx[G1], s_cy[G1], s_cz[G1], s_cn[G1];
    if (t < G1) {
        int s  = g0 + t;
        int fi = g_fps1[b * NP1 + s];
        s_cx[t] = g_nx1[(b * NP1 + s) * 3 + 0];
        s_cy[t] = g_nx1[(b * NP1 + s) * 3 + 1];
        s_cz[t] = g_nx1[(b * NP1 + s) * 3 + 2];
        s_cn[t] = g_norms1[b * N1 + fi];
    }
    __syncthreads();

    float cxr[G1], cyr[G1], czr[G1], cnr[G1];
#pragma unroll
    for (int g = 0; g < G1; ++g) {
        cxr[g] = s_cx[g]; cyr[g] = s_cy[g]; czr[g] = s_cz[g]; cnr[g] = s_cn[g];
    }

    const float* X  = xyz + (size_t)b * 6 * N1;
    const float* Y  = X + N1;
    const float* Z  = X + 2 * N1;
    const float* NN = g_norms1 + b * N1;
    const float r2  = (float)(0.025 * 0.025);
    int p0 = split * (N1 / SP1);

#pragma unroll 1
    for (int i = 0; i < (N1 / SP1) / 256; ++i) {
        int p = p0 + i * 256 + t;
        float x = X[p], y = Y[p], z = Z[p], nn = NN[p];
#pragma unroll
        for (int g = 0; g < G1; ++g) {
            float dot = cxr[g] * x + cyr[g] * y + czr[g] * z;
            float sq  = (cnr[g] + nn) - 2.0f * dot;   // mimic ref formula
            if (sq <= r2) {
                int cent = b * NP1 + g0 + g;
                int pos = atomicAdd(&g_ccnt1[cent], 1);
                if (pos < CCAP) g_coll1[cent * CCAP + pos] = p;
            }
        }
    }
}

// sort + truncate per centroid
__global__ void k_bqfix1() {
    int idx = blockIdx.x * 256 + threadIdx.x;
    if (idx >= B * NP1) return;
    int m = min(g_ccnt1[idx], CCAP);
    int buf[CCAP];
    for (int i = 0; i < m; ++i) buf[i] = g_coll1[idx * CCAP + i];
    for (int i = 1; i < m; ++i) {
        int key = buf[i], j = i - 1;
        while (j >= 0 && buf[j] > key) { buf[j + 1] = buf[j]; --j; }
        buf[j + 1] = key;
    }
    int K = min(m, NS1);
    if (K == 0) { buf[0] = g_fps1[idx]; K = 1; }
    g_cnt1[idx] = K;
    for (int i = 0; i < K; ++i) g_list1[idx * 64 + i] = buf[i];
}

// ---------------- ball query 2 ---------------------------------------------
__global__ void __launch_bounds__(128) k_bq2() {
    int b  = blockIdx.x >> 5;
    int g0 = (blockIdx.x & 31) * 8;
    int t  = threadIdx.x;
    __shared__ float s_cx[8], s_cy[8], s_cz[8], s_cn[8];
    __shared__ int   s_cnt[8];
    __shared__ int   s_buf[8][CAP];

    if (t < 8) {
        int s  = g0 + t;
        int fi = g_fps2[b * NP2 + s];
        s_cx[t] = g_nx2[(b * NP2 + s) * 3 + 0];
        s_cy[t] = g_nx2[(b * NP2 + s) * 3 + 1];
        s_cz[t] = g_nx2[(b * NP2 + s) * 3 + 2];
        s_cn[t] = g_norms2[b * N2 + fi];
        s_cnt[t] = 0;
    }
    __syncthreads();

    const float r2 = (float)(0.05 * 0.05);
    for (int p = t; p < N2; p += 128) {
        float x  = g_nx1[(b * N2 + p) * 3 + 0];
        float y  = g_nx1[(b * N2 + p) * 3 + 1];
        float z  = g_nx1[(b * N2 + p) * 3 + 2];
        float nn = g_norms2[b * N2 + p];
#pragma unroll
        for (int g = 0; g < 8; ++g) {
            float dot = s_cx[g] * x + s_cy[g] * y + s_cz[g] * z;
            float sq  = (s_cn[g] + nn) - 2.0f * dot;
            if (sq <= r2) {
                int pos = atomicAdd(&s_cnt[g], 1);
                if (pos < CAP) s_buf[g][pos] = p;
            }
        }
    }
    __syncthreads();

    if (t < 8) {
        int s = g0 + t;
        int m = min(s_cnt[t], CAP);
        int* bf = s_buf[t];
        for (int i = 1; i < m; ++i) {
            int key = bf[i], j = i - 1;
            while (j >= 0 && bf[j] > key) { bf[j + 1] = bf[j]; --j; }
            bf[j + 1] = key;
        }
        int K = min(m, NS2);
        if (K == 0) { bf[0] = g_fps2[b * NP2 + s]; K = 1; }
        g_cnt2[b * NP2 + s] = K;
        for (int i = 0; i < K; ++i) g_list2[(b * NP2 + s) * 64 + i] = bf[i];
    }
}

// ---------------- SA1 MLP (6->64->64->128) + max, distinct points only -----
__global__ void __launch_bounds__(128) k_mlp1(const float* __restrict__ xyz,
                                              const float* __restrict__ b1,
                                              const float* __restrict__ b2,
                                              const float* __restrict__ b3) {
    int bs = blockIdx.x;          // b*512 + s
    int b  = bs >> 9;
    int t  = threadIdx.x;
    __shared__ float s_f[6], s_h1[64], s_h2[64], s_c[3];
    if (t < 3) s_c[t] = g_nx1[bs * 3 + t];
    int K = g_cnt1[bs];
    float macc = -3.402823466e38f;
    __syncthreads();

    for (int k = 0; k < K; ++k) {
        int n = g_list1[bs * 64 + k];
        if (t < 6) {
            float v = xyz[((size_t)b * 6 + t) * N1 + n];
            if (t < 3) v -= s_c[t];
            s_f[t] = v;
        }
        __syncthreads();
        if (t < 64) {
            float a = b1[t];
#pragma unroll
            for (int c = 0; c < 6; ++c) a = fmaf(g_w1t[c * 64 + t], s_f[c], a);
            s_h1[t] = fmaxf(a, 0.0f);
        }
        __syncthreads();
        if (t < 64) {
            float a = b2[t];
#pragma unroll
            for (int c = 0; c < 64; ++c) a = fmaf(g_w2t[c * 64 + t], s_h1[c], a);
            s_h2[t] = fmaxf(a, 0.0f);
        }
        __syncthreads();
        {
            float a = b3[t];
#pragma unroll
            for (int c = 0; c < 64; ++c) a = fmaf(g_w3t[c * 128 + t], s_h2[c], a);
            macc = fmaxf(macc, fmaxf(a, 0.0f));
        }
        __syncthreads();
    }
    g_feat1[bs * 128 + t] = macc;
}

// ---------------- SA2 MLP (131->128->128->285) + max -----------------------
__global__ void __launch_bounds__(288) k_mlp2(const float* __restrict__ b1,
                                              const float* __restrict__ b2,
                                              const float* __restrict__ b3,
                                              float* __restrict__ out) {
    int bs = blockIdx.x;          // b*256 + s
    int b  = bs >> 8;
    int t  = threadIdx.x;
    __shared__ float s_f[131], s_h1[128], s_h2[128], s_c[3];
    if (t < 3) s_c[t] = g_nx2[bs * 3 + t];
    int K = g_cnt2[bs];
    float macc = -3.402823466e38f;
    __syncthreads();

    for (int k = 0; k < K; ++k) {
        int n = g_list2[bs * 64 + k];
        if (t < 131) {
            float v;
            if (t < 3) v = g_nx1[(b * N2 + n) * 3 + t] - s_c[t];
            else       v = g_feat1[(b * N2 + n) * 128 + (t - 3)];
            s_f[t] = v;
        }
        __syncthreads();
        if (t < 128) {
            float a = b1[t];
#pragma unroll
            for (int c = 0; c < 131; ++c) a = fmaf(g_w1t2[c * 128 + t], s_f[c], a);
            s_h1[t] = fmaxf(a, 0.0f);
        }
        __syncthreads();
        if (t < 128) {
            float a = b2[t];
#pragma unroll
            for (int c = 0; c < 128; ++c) a = fmaf(g_w2t2[c * 128 + t], s_h1[c], a);
            s_h2[t] = fmaxf(a, 0.0f);
        }
        __syncthreads();
        if (t < 285) {
            float a = b3[t];
#pragma unroll
            for (int c = 0; c < 128; ++c) a = fmaf(g_w3t2[c * 285 + t], s_h2[c], a);
            macc = fmaxf(macc, fmaxf(a, 0.0f));
        }
        __syncthreads();
    }
    if (t < 285) out[B * 3 * NP2 + bs * 285 + t] = macc;  // l2_points (B,256,285)
}

// ---------------- l2_xyz output: (B,3,256) ---------------------------------
__global__ void k_out_xyz(float* __restrict__ out) {
    int i = blockIdx.x * 256 + threadIdx.x;
    if (i < B * 3 * NP2) {
        int b = i / (3 * NP2);
        int r = i % (3 * NP2);
        int d = r / NP2;
        int s = r % NP2;
        out[i] = g_nx2[(b * NP2 + s) * 3 + d];
    }
}

// ---------------- launch ----------------------------------------------------
extern "C" void kernel_launch(void* const* d_in, const int* in_sizes, int n_in,
                              void* d_out, int out_size) {
    (void)in_sizes; (void)n_in; (void)out_size;
    const float* xyz = (const float*)d_in[0];
    const float* w1  = (const float*)d_in[1];  const float* bb1 = (const float*)d_in[2];
    const float* w2  = (const float*)d_in[3];  const float* bb2 = (const float*)d_in[4];
    const float* w3  = (const float*)d_in[5];  const float* bb3 = (const float*)d_in[6];
    const float* u1  = (const float*)d_in[7];  const float* cc1 = (const float*)d_in[8];
    const float* u2  = (const float*)d_in[9];  const float* cc2 = (const float*)d_in[10];
    const float* u3  = (const float*)d_in[11]; const float* cc3 = (const float*)d_in[12];
    float* out = (float*)d_out;

    k_transpose_all<<<(82304 + B * NP1 + 255) / 256, 256>>>(w1, w2, w3, u1, u2, u3);
    k_norms1<<<(B * N1) / 256, 256>>>(xyz);
    k_fps1<<<B * FCL, 512>>>(xyz);
    k_bq1c<<<B * 32 * SP1, 256>>>(xyz);
    k_bqfix1<<<(B * NP1 + 255) / 256, 256>>>();
    k_mlp1<<<B * NP1, 128>>>(xyz, bb1, bb2, bb3);
    k_norms2<<<(B * N2 + 255) / 256, 256>>>();
    k_fps2<<<B, 32>>>();
    k_bq2<<<B * 32, 128>>>();
    k_mlp2<<<B * NP2, 288>>>(cc1, cc2, cc3, out);
    k_out_xyz<<<(B * 3 * NP2 + 255) / 256, 256>>>(out);
}

// round 13
// speedup vs baseline: 1.5919x; 1.5919x over previous
#include <cuda_runtime.h>
#include <math.h>
#include <stdint.h>

#define B   8
#define N1  32768
#define NP1 512
#define NS1 32
#define N2  512
#define NP2 256
#define NS2 64
#define CAP 128
#define CCAP 96

#define FCL 8          // cluster size for fps1
#define FPTS 4096      // points per CTA
#define FPPT 8         // points per thread (512 threads)

#define G1  16         // centroids per bq1 block
#define SP1 8          // point splits per centroid group

typedef unsigned long long ull;

// ---------------- scratch (device globals; no allocations) ----------------
__device__ float g_w1t [6  * 64 ];
__device__ float g_w2t [64 * 64 ];
__device__ float g_w3t [64 * 128];
__device__ float g_w1t2[131 * 128];
__device__ float g_w2t2[128 * 128];
__device__ float g_w3t2[128 * 285];

__device__ float g_norms1[B * N1];
__device__ int   g_fps1 [B * NP1];
__device__ float g_nx1  [B * NP1 * 3];
__device__ int   g_cnt1 [B * NP1];
__device__ int   g_list1[B * NP1 * 64];
__device__ float g_feat1[B * NP1 * 128];
__device__ int   g_ccnt1[B * NP1];
__device__ int   g_coll1[B * NP1 * CCAP];

__device__ float g_norms2[B * N2];
__device__ int   g_fps2 [B * NP2];
__device__ float g_nx2  [B * NP2 * 3];
__device__ int   g_cnt2 [B * NP2];
__device__ int   g_list2[B * NP2 * 64];

// ---------------- cluster helpers ------------------------------------------
__device__ __forceinline__ uint32_t s2u(const void* p) {
    return (uint32_t)__cvta_generic_to_shared(p);
}
__device__ __forceinline__ unsigned cl_rank() {
    unsigned r; asm("mov.u32 %0, %%cluster_ctarank;" : "=r"(r)); return r;
}
__device__ __forceinline__ void cluster_sync() {
    asm volatile("barrier.cluster.arrive.aligned;" ::: "memory");
    asm volatile("barrier.cluster.wait.aligned;" ::: "memory");
}
__device__ __forceinline__ void st_remote_u64(uint32_t laddr, unsigned rank, ull v) {
    asm volatile("{ .reg .b32 ra; mapa.shared::cluster.u32 ra, %0, %1; "
                 "st.shared::cluster.b64 [ra], %2; }"
                 :: "r"(laddr), "r"(rank), "l"(v) : "memory");
}
__device__ __forceinline__ void st_remote_u32(uint32_t laddr, unsigned rank, unsigned v) {
    asm volatile("{ .reg .b32 ra; mapa.shared::cluster.u32 ra, %0, %1; "
                 "st.shared::cluster.b32 [ra], %2; }"
                 :: "r"(laddr), "r"(rank), "r"(v) : "memory");
}
__device__ __forceinline__ void arrive_remote(uint32_t lbar, unsigned rank) {
    asm volatile("{ .reg .b32 ra; mapa.shared::cluster.u32 ra, %0, %1; "
                 "mbarrier.arrive.release.cluster.shared::cluster.b64 _, [ra]; }"
                 :: "r"(lbar), "r"(rank) : "memory");
}
__device__ __forceinline__ void mbar_wait_cluster(uint32_t mbar, unsigned parity) {
    asm volatile(
        "{\n\t"
        ".reg .pred P1;\n\t"
        "WAIT_LOOP_%=:\n\t"
        "mbarrier.try_wait.parity.acquire.cluster.shared::cta.b64 P1, [%0], %1, 0x989680;\n\t"
        "@P1 bra.uni WAIT_DONE_%=;\n\t"
        "bra.uni WAIT_LOOP_%=;\n\t"
        "WAIT_DONE_%=:\n\t"
        "}" :: "r"(mbar), "r"(parity) : "memory");
}

// ---------------- weight transpose + counter init ---------------------------
__global__ void k_transpose_all(const float* __restrict__ w1, const float* __restrict__ w2,
                                const float* __restrict__ w3, const float* __restrict__ u1,
                                const float* __restrict__ u2, const float* __restrict__ u3) {
    int i = blockIdx.x * 256 + threadIdx.x;
    if (i < 384) {                              // 64x6
        int o = i / 6, c = i % 6;               g_w1t [c * 64  + o] = w1[i];
    } else if (i < 4480) {                      // 64x64
        int j = i - 384;  int o = j / 64,  c = j % 64;  g_w2t [c * 64  + o] = w2[j];
    } else if (i < 12672) {                     // 128x64
        int j = i - 4480; int o = j / 64,  c = j % 64;  g_w3t [c * 128 + o] = w3[j];
    } else if (i < 29440) {                     // 128x131
        int j = i - 12672;int o = j / 131, c = j % 131; g_w1t2[c * 128 + o] = u1[j];
    } else if (i < 45824) {                     // 128x128
        int j = i - 29440;int o = j / 128, c = j % 128; g_w2t2[c * 128 + o] = u2[j];
    } else if (i < 82304) {                     // 285x128
        int j = i - 45824;int o = j / 128, c = j % 128; g_w3t2[c * 285 + o] = u3[j];
    } else if (i < 82304 + B * NP1) {           // zero bq1 collection counters
        g_ccnt1[i - 82304] = 0;
    }
}

// ---------------- squared norms --------------------------------------------
__global__ void k_norms1(const float* __restrict__ xyz) {
    int i = blockIdx.x * 256 + threadIdx.x;
    if (i < B * N1) {
        int b = i >> 15, n = i & (N1 - 1);
        const float* base = xyz + (size_t)b * 6 * N1;
        float x = base[n], y = base[N1 + n], z = base[2 * N1 + n];
        g_norms1[i] = (x * x + y * y) + z * z;
    }
}

__global__ void k_norms2() {
    int i = blockIdx.x * 256 + threadIdx.x;
    if (i < B * N2) {
        float x = g_nx1[i * 3], y = g_nx1[i * 3 + 1], z = g_nx1[i * 3 + 2];
        g_norms2[i] = (x * x + y * y) + z * z;
    }
}

// ---------------- FPS stage 1: cluster of 8 CTAs per batch ------------------
// (round-9 structure: REDUX reductions, warp-0 agent, 3-store exchange)
__global__ void __launch_bounds__(512, 1) __cluster_dims__(FCL, 1, 1)
k_fps1(const float* __restrict__ xyz) {
    int b = blockIdx.x / FCL;
    unsigned rank = cl_rank();
    int tid = threadIdx.x;
    int lane = tid & 31, warp = tid >> 5;
    const float* X = xyz + (size_t)b * 6 * N1;
    const float* Y = X + N1;
    const float* Z = X + 2 * N1;
    unsigned base = rank * FPTS;

    float px[FPPT], py[FPPT], pz[FPPT], dist[FPPT];
#pragma unroll
    for (int j = 0; j < FPPT; ++j) {
        int p = base + j * 512 + tid;
        px[j] = X[p]; py[j] = Y[p]; pz[j] = Z[p];
        dist[j] = 1e10f;
    }

    __shared__ unsigned s_wv[16], s_wbi[16];
    __shared__ float s_wcx[16], s_wcy[16], s_wcz[16];
    __shared__ ull   s_key[2][FCL];
    __shared__ ull   s_cxy[2][FCL];
    __shared__ float s_cz [2][FCL];
    __shared__ ull   s_mbar;

    uint32_t bar = s2u(&s_mbar);
    if (tid == 0) {
        asm volatile("mbarrier.init.shared.b64 [%0], %1;" :: "r"(bar), "r"((unsigned)FCL) : "memory");
        asm volatile("fence.mbarrier_init.release.cluster;" ::: "memory");
    }
    __syncthreads();
    cluster_sync();

    unsigned far = 0;
    float cx = X[0], cy = Y[0], cz = Z[0];

    for (int it = 0; it < NP1; ++it) {
        unsigned par = (unsigned)(it & 1);
        if (rank == 0 && tid == 0) {
            g_fps1[b * NP1 + it] = (int)far;
            g_nx1[(b * NP1 + it) * 3 + 0] = cx;
            g_nx1[(b * NP1 + it) * 3 + 1] = cy;
            g_nx1[(b * NP1 + it) * 3 + 2] = cz;
        }
        // update dists (parallel) + thread-local argmax via packed-key tree
        ull kk[FPPT];
#pragma unroll
        for (int j = 0; j < FPPT; ++j) {
            float dx = px[j] - cx, dy = py[j] - cy, dz = pz[j] - cz;
            float d  = dx * dx + dy * dy + dz * dz;
            float nd = fminf(dist[j], d);
            dist[j] = nd;
            unsigned bij = base + (unsigned)(j * 512 + tid);
            kk[j] = ((ull)__float_as_uint(nd) << 32) | (ull)(0xFFFFFFFFu - bij);
        }
#pragma unroll
        for (int s = FPPT / 2; s; s >>= 1)
#pragma unroll
            for (int i = 0; i < s; ++i)
                if (kk[i + s] > kk[i]) kk[i] = kk[i + s];
        unsigned vb = (unsigned)(kk[0] >> 32);
        unsigned bi = 0xFFFFFFFFu - (unsigned)(kk[0] & 0xFFFFFFFFull);

        // warp reduce via REDUX (max value, then min index among max holders)
        unsigned wmax = __reduce_max_sync(0xFFFFFFFFu, vb);
        unsigned cand = (vb == wmax) ? bi : 0xFFFFFFFFu;
        unsigned wbi  = __reduce_min_sync(0xFFFFFFFFu, cand);

        // winner coords from winner thread's registers (lane/j decoded from wbi)
        {
            unsigned lw = wbi & 31u;
            unsigned jw = (wbi & 4095u) >> 9;
            float sx = px[0], sy = py[0], sz = pz[0];
#pragma unroll
            for (int j = 1; j < FPPT; ++j) {
                if (jw == (unsigned)j) { sx = px[j]; sy = py[j]; sz = pz[j]; }
            }
            sx = __shfl_sync(0xFFFFFFFFu, sx, lw);
            sy = __shfl_sync(0xFFFFFFFFu, sy, lw);
            sz = __shfl_sync(0xFFFFFFFFu, sz, lw);
            if (lane == 0) {
                s_wv[warp] = wmax; s_wbi[warp] = wbi;
                s_wcx[warp] = sx;  s_wcy[warp] = sy; s_wcz[warp] = sz;
            }
        }
        __syncthreads();

        if (tid < 32) {
            unsigned v  = (tid < 16) ? s_wv[tid]  : 0u;
            unsigned bw = (tid < 16) ? s_wbi[tid] : 0xFFFFFFFFu;
            unsigned vmax = __reduce_max_sync(0xFFFFFFFFu, v);
            unsigned c2   = (v == vmax && tid < 16) ? bw : 0xFFFFFFFFu;
            unsigned bbi  = __reduce_min_sync(0xFFFFFFFFu, c2);
            if (tid < FCL) {
                unsigned w = (bbi & 511u) >> 5;        // winning warp in this CTA
                float bx = s_wcx[w], by = s_wcy[w], bz = s_wcz[w];
                ull key = ((ull)vmax << 32) | (ull)(0xFFFFFFFFu - bbi);
                ull cxy;
                asm("mov.b64 %0, {%1, %2};" : "=l"(cxy) : "f"(bx), "f"(by));
                st_remote_u64(s2u(&s_key[par][rank]), (unsigned)tid, key);
                st_remote_u64(s2u(&s_cxy[par][rank]), (unsigned)tid, cxy);
                st_remote_u32(s2u(&s_cz [par][rank]), (unsigned)tid, __float_as_uint(bz));
                arrive_remote(bar, (unsigned)tid);
            }
        }

        mbar_wait_cluster(bar, par);

        // global best among the 8 slots: depth-3 tree; slot decoded from index
        ull k0 = s_key[par][0], k1 = s_key[par][1], k2 = s_key[par][2], k3 = s_key[par][3];
        ull k4 = s_key[par][4], k5 = s_key[par][5], k6 = s_key[par][6], k7 = s_key[par][7];
        ull m0 = (k1 > k0) ? k1 : k0;
        ull m1 = (k3 > k2) ? k3 : k2;
        ull m2 = (k5 > k4) ? k5 : k4;
        ull m3 = (k7 > k6) ? k7 : k6;
        ull n0 = (m1 > m0) ? m1 : m0;
        ull n1 = (m3 > m2) ? m3 : m2;
        ull best = (n1 > n0) ? n1 : n0;
        far = 0xFFFFFFFFu - (unsigned)(best & 0xFFFFFFFFull);
        unsigned bs = far >> 12;                   // 4096 points per CTA
        ull cxy = s_cxy[par][bs];
        float ncx, ncy;
        asm("mov.b64 {%0, %1}, %2;" : "=f"(ncx), "=f"(ncy) : "l"(cxy));
        cx = ncx; cy = ncy; cz = s_cz[par][bs];
    }
    cluster_sync();
}

// ---------------- FPS stage 2: one warp per batch, all-register -------------
__global__ void __launch_bounds__(32, 1) k_fps2() {
    int b = blockIdx.x;
    int lane = threadIdx.x;

    float px[16], py[16], pz[16], dist[16];
#pragma unroll
    for (int j = 0; j < 16; ++j) {
        int p = j * 32 + lane;
        px[j] = g_nx1[(b * NP1 + p) * 3 + 0];
        py[j] = g_nx1[(b * NP1 + p) * 3 + 1];
        pz[j] = g_nx1[(b * NP1 + p) * 3 + 2];
        dist[j] = 1e10f;
    }

    unsigned far = 0;
    float cx = __shfl_sync(0xFFFFFFFFu, px[0], 0);
    float cy = __shfl_sync(0xFFFFFFFFu, py[0], 0);
    float cz = __shfl_sync(0xFFFFFFFFu, pz[0], 0);

    for (int it = 0; it < NP2; ++it) {
        if (lane == 0) {
            g_fps2[b * NP2 + it] = (int)far;
            g_nx2[(b * NP2 + it) * 3 + 0] = cx;
            g_nx2[(b * NP2 + it) * 3 + 1] = cy;
            g_nx2[(b * NP2 + it) * 3 + 2] = cz;
        }
        ull kk[16];
#pragma unroll
        for (int j = 0; j < 16; ++j) {
            float dx = px[j] - cx, dy = py[j] - cy, dz = pz[j] - cz;
            float d  = dx * dx + dy * dy + dz * dz;
            float nd = fminf(dist[j], d);
            dist[j] = nd;
            unsigned bij = (unsigned)(j * 32 + lane);
            kk[j] = ((ull)__float_as_uint(nd) << 32) | (ull)(0xFFFFFFFFu - bij);
        }
#pragma unroll
        for (int s = 8; s; s >>= 1)
#pragma unroll
            for (int i = 0; i < s; ++i)
                if (kk[i + s] > kk[i]) kk[i] = kk[i + s];
        unsigned vb = (unsigned)(kk[0] >> 32);
        unsigned bi = 0xFFFFFFFFu - (unsigned)(kk[0] & 0xFFFFFFFFull);

        unsigned wmax = __reduce_max_sync(0xFFFFFFFFu, vb);
        unsigned cand = (vb == wmax) ? bi : 0xFFFFFFFFu;
        unsigned wbi  = __reduce_min_sync(0xFFFFFFFFu, cand);

        unsigned lw = wbi & 31u;
        unsigned jw = wbi >> 5;
        float sx = px[0], sy = py[0], sz = pz[0];
#pragma unroll
        for (int j = 1; j < 16; ++j) {
            if (jw == (unsigned)j) { sx = px[j]; sy = py[j]; sz = pz[j]; }
        }
        cx = __shfl_sync(0xFFFFFFFFu, sx, lw);
        cy = __shfl_sync(0xFFFFFFFFu, sy, lw);
        cz = __shfl_sync(0xFFFFFFFFu, sz, lw);
        far = wbi;
    }
}

// ---------------- ball query 1: 16 centroids x 8 point-splits ---------------
// __launch_bounds__(256, 3): cap regs at 85 so 3 CTAs/SM fit (occ 24% -> 37%)
__global__ void __launch_bounds__(256, 3) k_bq1c(const float* __restrict__ xyz) {
    int bid   = blockIdx.x;
    int b     = bid / (32 * SP1);
    int rem   = bid % (32 * SP1);
    int grp   = rem / SP1;
    int split = rem % SP1;
    int g0    = grp * G1;
    int t     = threadIdx.x;

    __shared__ float s_cx[G1], s_cy[G1], s_cz[G1], s_cn[G1];
    if (t < G1) {
        int s  = g0 + t;
        int fi = g_fps1[b * NP1 + s];
        s_cx[t] = g_nx1[(b * NP1 + s) * 3 + 0];
        s_cy[t] = g_nx1[(b * NP1 + s) * 3 + 1];
        s_cz[t] = g_nx1[(b * NP1 + s) * 3 + 2];
        s_cn[t] = g_norms1[b * N1 + fi];
    }
    __syncthreads();

    float cxr[G1], cyr[G1], czr[G1], cnr[G1];
#pragma unroll
    for (int g = 0; g < G1; ++g) {
        cxr[g] = s_cx[g]; cyr[g] = s_cy[g]; czr[g] = s_cz[g]; cnr[g] = s_cn[g];
    }

    const float* X  = xyz + (size_t)b * 6 * N1;
    const float* Y  = X + N1;
    const float* Z  = X + 2 * N1;
    const float* NN = g_norms1 + b * N1;
    const float r2  = (float)(0.025 * 0.025);
    int p0 = split * (N1 / SP1);

#pragma unroll 1
    for (int i = 0; i < (N1 / SP1) / 256; ++i) {
        int p = p0 + i * 256 + t;
        float x = X[p], y = Y[p], z = Z[p], nn = NN[p];
#pragma unroll
        for (int g = 0; g < G1; ++g) {
            float dot = cxr[g] * x + cyr[g] * y + czr[g] * z;
            float sq  = (cnr[g] + nn) - 2.0f * dot;   // mimic ref formula
            if (sq <= r2) {
                int cent = b * NP1 + g0 + g;
                int pos = atomicAdd(&g_ccnt1[cent], 1);
                if (pos < CCAP) g_coll1[cent * CCAP + pos] = p;
            }
        }
    }
}

// sort + truncate per centroid
__global__ void k_bqfix1() {
    int idx = blockIdx.x * 256 + threadIdx.x;
    if (idx >= B * NP1) return;
    int m = min(g_ccnt1[idx], CCAP);
    int buf[CCAP];
    for (int i = 0; i < m; ++i) buf[i] = g_coll1[idx * CCAP + i];
    for (int i = 1; i < m; ++i) {
        int key = buf[i], j = i - 1;
        while (j >= 0 && buf[j] > key) { buf[j + 1] = buf[j]; --j; }
        buf[j + 1] = key;
    }
    int K = min(m, NS1);
    if (K == 0) { buf[0] = g_fps1[idx]; K = 1; }
    g_cnt1[idx] = K;
    for (int i = 0; i < K; ++i) g_list1[idx * 64 + i] = buf[i];
}

// ---------------- ball query 2 ---------------------------------------------
__global__ void __launch_bounds__(128) k_bq2() {
    int b  = blockIdx.x >> 5;
    int g0 = (blockIdx.x & 31) * 8;
    int t  = threadIdx.x;
    __shared__ float s_cx[8], s_cy[8], s_cz[8], s_cn[8];
    __shared__ int   s_cnt[8];
    __shared__ int   s_buf[8][CAP];

    if (t < 8) {
        int s  = g0 + t;
        int fi = g_fps2[b * NP2 + s];
        s_cx[t] = g_nx2[(b * NP2 + s) * 3 + 0];
        s_cy[t] = g_nx2[(b * NP2 + s) * 3 + 1];
        s_cz[t] = g_nx2[(b * NP2 + s) * 3 + 2];
        s_cn[t] = g_norms2[b * N2 + fi];
        s_cnt[t] = 0;
    }
    __syncthreads();

    const float r2 = (float)(0.05 * 0.05);
    for (int p = t; p < N2; p += 128) {
        float x  = g_nx1[(b * N2 + p) * 3 + 0];
        float y  = g_nx1[(b * N2 + p) * 3 + 1];
        float z  = g_nx1[(b * N2 + p) * 3 + 2];
        float nn = g_norms2[b * N2 + p];
#pragma unroll
        for (int g = 0; g < 8; ++g) {
            float dot = s_cx[g] * x + s_cy[g] * y + s_cz[g] * z;
            float sq  = (s_cn[g] + nn) - 2.0f * dot;
            if (sq <= r2) {
                int pos = atomicAdd(&s_cnt[g], 1);
                if (pos < CAP) s_buf[g][pos] = p;
            }
        }
    }
    __syncthreads();

    if (t < 8) {
        int s = g0 + t;
        int m = min(s_cnt[t], CAP);
        int* bf = s_buf[t];
        for (int i = 1; i < m; ++i) {
            int key = bf[i], j = i - 1;
            while (j >= 0 && bf[j] > key) { bf[j + 1] = bf[j]; --j; }
            bf[j + 1] = key;
        }
        int K = min(m, NS2);
        if (K == 0) { bf[0] = g_fps2[b * NP2 + s]; K = 1; }
        g_cnt2[b * NP2 + s] = K;
        for (int i = 0; i < K; ++i) g_list2[(b * NP2 + s) * 64 + i] = bf[i];
    }
}

// ---------------- SA1 MLP (6->64->64->128) + max, distinct points only -----
__global__ void __launch_bounds__(128) k_mlp1(const float* __restrict__ xyz,
                                              const float* __restrict__ b1,
                                              const float* __restrict__ b2,
                                              const float* __restrict__ b3) {
    int bs = blockIdx.x;          // b*512 + s
    int b  = bs >> 9;
    int t  = threadIdx.x;
    __shared__ float s_f[6], s_h1[64], s_h2[64], s_c[3];
    if (t < 3) s_c[t] = g_nx1[bs * 3 + t];
    int K = g_cnt1[bs];
    float macc = -3.402823466e38f;
    __syncthreads();

    for (int k = 0; k < K; ++k) {
        int n = g_list1[bs * 64 + k];
        if (t < 6) {
            float v = xyz[((size_t)b * 6 + t) * N1 + n];
            if (t < 3) v -= s_c[t];
            s_f[t] = v;
        }
        __syncthreads();
        if (t < 64) {
            float a = b1[t];
#pragma unroll
            for (int c = 0; c < 6; ++c) a = fmaf(g_w1t[c * 64 + t], s_f[c], a);
            s_h1[t] = fmaxf(a, 0.0f);
        }
        __syncthreads();
        if (t < 64) {
            float a = b2[t];
#pragma unroll
            for (int c = 0; c < 64; ++c) a = fmaf(g_w2t[c * 64 + t], s_h1[c], a);
            s_h2[t] = fmaxf(a, 0.0f);
        }
        __syncthreads();
        {
            float a = b3[t];
#pragma unroll
            for (int c = 0; c < 64; ++c) a = fmaf(g_w3t[c * 128 + t], s_h2[c], a);
            macc = fmaxf(macc, fmaxf(a, 0.0f));
        }
        __syncthreads();
    }
    g_feat1[bs * 128 + t] = macc;
}

// ---------------- SA2 MLP (131->128->128->285) + max -----------------------
__global__ void __launch_bounds__(288) k_mlp2(const float* __restrict__ b1,
                                              const float* __restrict__ b2,
                                              const float* __restrict__ b3,
                                              float* __restrict__ out) {
    int bs = blockIdx.x;          // b*256 + s
    int b  = bs >> 8;
    int t  = threadIdx.x;
    __shared__ float s_f[131], s_h1[128], s_h2[128], s_c[3];
    if (t < 3) s_c[t] = g_nx2[bs * 3 + t];
    int K = g_cnt2[bs];
    float macc = -3.402823466e38f;
    __syncthreads();

    for (int k = 0; k < K; ++k) {
        int n = g_list2[bs * 64 + k];
        if (t < 131) {
            float v;
            if (t < 3) v = g_nx1[(b * N2 + n) * 3 + t] - s_c[t];
            else       v = g_feat1[(b * N2 + n) * 128 + (t - 3)];
            s_f[t] = v;
        }
        __syncthreads();
        if (t < 128) {
            float a = b1[t];
#pragma unroll
            for (int c = 0; c < 131; ++c) a = fmaf(g_w1t2[c * 128 + t], s_f[c], a);
            s_h1[t] = fmaxf(a, 0.0f);
        }
        __syncthreads();
        if (t < 128) {
            float a = b2[t];
#pragma unroll
            for (int c = 0; c < 128; ++c) a = fmaf(g_w2t2[c * 128 + t], s_h1[c], a);
            s_h2[t] = fmaxf(a, 0.0f);
        }
        __syncthreads();
        if (t < 285) {
            float a = b3[t];
#pragma unroll
            for (int c = 0; c < 128; ++c) a = fmaf(g_w3t2[c * 285 + t], s_h2[c], a);
            macc = fmaxf(macc, fmaxf(a, 0.0f));
        }
        __syncthreads();
    }
    if (t < 285) out[B * 3 * NP2 + bs * 285 + t] = macc;  // l2_points (B,256,285)
}

// ---------------- l2_xyz output: (B,3,256) ---------------------------------
__global__ void k_out_xyz(float* __restrict__ out) {
    int i = blockIdx.x * 256 + threadIdx.x;
    if (i < B * 3 * NP2) {
        int b = i / (3 * NP2);
        int r = i % (3 * NP2);
        int d = r / NP2;
        int s = r % NP2;
        out[i] = g_nx2[(b * NP2 + s) * 3 + d];
    }
}

// ---------------- launch ----------------------------------------------------
extern "C" void kernel_launch(void* const* d_in, const int* in_sizes, int n_in,
                              void* d_out, int out_size) {
    (void)in_sizes; (void)n_in; (void)out_size;
    const float* xyz = (const float*)d_in[0];
    const float* w1  = (const float*)d_in[1];  const float* bb1 = (const float*)d_in[2];
    const float* w2  = (const float*)d_in[3];  const float* bb2 = (const float*)d_in[4];
    const float* w3  = (const float*)d_in[5];  const float* bb3 = (const float*)d_in[6];
    const float* u1  = (const float*)d_in[7];  const float* cc1 = (const float*)d_in[8];
    const float* u2  = (const float*)d_in[9];  const float* cc2 = (const float*)d_in[10];
    const float* u3  = (const float*)d_in[11]; const float* cc3 = (const float*)d_in[12];
    float* out = (float*)d_out;

    k_transpose_all<<<(82304 + B * NP1 + 255) / 256, 256>>>(w1, w2, w3, u1, u2, u3);
    k_norms1<<<(B * N1) / 256, 256>>>(xyz);
    k_fps1<<<B * FCL, 512>>>(xyz);
    k_bq1c<<<B * 32 * SP1, 256>>>(xyz);
    k_bqfix1<<<(B * NP1 + 255) / 256, 256>>>();
    k_mlp1<<<B * NP1, 128>>>(xyz, bb1, bb2, bb3);
    k_norms2<<<(B * N2 + 255) / 256, 256>>>();
    k_fps2<<<B, 32>>>();
    k_bq2<<<B * 32, 128>>>();
    k_mlp2<<<B * NP2, 288>>>(cc1, cc2, cc3, out);
    k_out_xyz<<<(B * 3 * NP2 + 255) / 256, 256>>>(out);
}